// round 3
// baseline (speedup 1.0000x reference)
#include <cuda_runtime.h>
#include <cstdint>

// Fused: conv3x3 (zero-pad bottom/right) -> +bias -> *scale -> maxpool2x2 -> clamp[0,1]
// x: [B,3,512,512] f32, w: [16,3,3,3], bias: [16], scale: [16,1,1]
// out: [B,16,256,256] f32
//
// One thread computes one pooled pixel for all 16 OC using packed f32x2 FMA
// (two horizontal conv columns per lane-pair -> 2 FMA/instr, 128 FMA/cyc/SM).

#define OCN 16
#define ICN 3
#define IH 512
#define IW 512
#define PH 256
#define PW 256

__device__ __forceinline__ unsigned long long pack2(float a, float b) {
    unsigned long long r;
    asm("mov.b64 %0, {%1, %2};" : "=l"(r) : "f"(a), "f"(b));
    return r;
}
__device__ __forceinline__ void unpack2(unsigned long long p, float& a, float& b) {
    asm("mov.b64 {%0, %1}, %2;" : "=f"(a), "=f"(b) : "l"(p));
}
__device__ __forceinline__ void fma2(unsigned long long& acc, unsigned long long a,
                                     unsigned long long b) {
    asm("fma.rn.f32x2 %0, %1, %2, %0;" : "+l"(acc) : "l"(a), "l"(b));
}
// d = a*b + c (non-accumulating form, for the bias/scale epilogue)
__device__ __forceinline__ unsigned long long fma2n(unsigned long long a, unsigned long long b,
                                                    unsigned long long c) {
    unsigned long long d;
    asm("fma.rn.f32x2 %0, %1, %2, %3;" : "=l"(d) : "l"(a), "l"(b), "l"(c));
    return d;
}

__global__ __launch_bounds__(128)
void conv_pool_clamp_kernel(const float* __restrict__ x,
                            const float* __restrict__ w,
                            const float* __restrict__ bias,
                            const float* __restrict__ scale,
                            float* __restrict__ out) {
    // Weights pre-duplicated {w,w} as 64-bit words for direct LDS.64 broadcast.
    __shared__ unsigned long long sw[OCN * ICN * 9];
    __shared__ unsigned long long ssc[OCN];   // {s, s}
    __shared__ unsigned long long sbs[OCN];   // {b*s, b*s}

    const int tid = threadIdx.x;
    for (int i = tid; i < OCN * ICN * 9; i += blockDim.x) {
        float v = w[i];
        sw[i] = pack2(v, v);
    }
    if (tid < OCN) {
        float s = scale[tid];
        float bs = bias[tid] * s;
        ssc[tid] = pack2(s, s);
        sbs[tid] = pack2(bs, bs);
    }
    __syncthreads();

    const int pw = blockIdx.x * blockDim.x + tid;   // 0..255
    const int ph = blockIdx.y;                      // 0..255
    const int bi = blockIdx.z;                      // 0..B-1
    if (pw >= PW) return;

    const int ih0 = ph * 2;
    const int iw0 = pw * 2;

    // Accumulators: per OC, top conv row (oh=2ph) and bottom conv row (oh=2ph+1),
    // each holding conv columns {2pw, 2pw+1} packed in f32x2.
    unsigned long long acc_t[OCN], acc_b[OCN];
#pragma unroll
    for (int o = 0; o < OCN; o++) { acc_t[o] = 0ull; acc_b[o] = 0ull; }

#pragma unroll
    for (int ic = 0; ic < ICN; ic++) {
        const float* xc = x + ((size_t)bi * ICN + ic) * (IH * IW);

        // 4x4 input patch, zero-padded bottom/right.
        float r[4][4];
#pragma unroll
        for (int rr = 0; rr < 4; rr++) {
            const int ih = ih0 + rr;
            float c0 = 0.f, c1 = 0.f, c2 = 0.f, c3 = 0.f;
            if (ih < IH) {
                const float* row = xc + (size_t)ih * IW;
                // cols iw0, iw0+1 always in-bounds (iw0 <= 510)
                float2 lo = *(const float2*)(row + iw0);
                c0 = lo.x; c1 = lo.y;
                if (iw0 + 2 < IW) {   // iw0 even: hi pair fully in or fully out
                    float2 hi = *(const float2*)(row + iw0 + 2);
                    c2 = hi.x; c3 = hi.y;
                }
            }
            r[rr][0] = c0; r[rr][1] = c1; r[rr][2] = c2; r[rr][3] = c3;
        }

        // Overlapping column pairs per row: p[rr][t] = {r[rr][t], r[rr][t+1]}
        unsigned long long p[4][3];
#pragma unroll
        for (int rr = 0; rr < 4; rr++) {
#pragma unroll
            for (int t = 0; t < 3; t++) p[rr][t] = pack2(r[rr][t], r[rr][t + 1]);
        }

#pragma unroll
        for (int oc = 0; oc < OCN; oc++) {
            const unsigned long long* wp = &sw[(oc * ICN + ic) * 9];
#pragma unroll
            for (int kh = 0; kh < 3; kh++) {
#pragma unroll
                for (int kw = 0; kw < 3; kw++) {
                    const unsigned long long w2 = wp[kh * 3 + kw];  // LDS.64 broadcast
                    fma2(acc_t[oc], p[kh][kw], w2);      // conv row oh = 2ph
                    fma2(acc_b[oc], p[kh + 1][kw], w2);  // conv row oh = 2ph+1
                }
            }
        }
    }

    // Epilogue: (y + bias) * scale  ->  max over 2x2  ->  clamp [0,1]
    float* ob = out + (((size_t)bi * OCN) * PH + ph) * PW + pw;
#pragma unroll
    for (int oc = 0; oc < OCN; oc++) {
        unsigned long long t = fma2n(acc_t[oc], ssc[oc], sbs[oc]);
        unsigned long long b = fma2n(acc_b[oc], ssc[oc], sbs[oc]);
        float t0, t1, b0, b1;
        unpack2(t, t0, t1);
        unpack2(b, b0, b1);
        float m = fmaxf(fmaxf(t0, t1), fmaxf(b0, b1));
        m = fminf(fmaxf(m, 0.0f), 1.0f);
        ob[(size_t)oc * (PH * PW)] = m;
    }
}

extern "C" void kernel_launch(void* const* d_in, const int* in_sizes, int n_in,
                              void* d_out, int out_size) {
    const float* x     = (const float*)d_in[0];
    const float* w     = (const float*)d_in[1];
    const float* bias  = (const float*)d_in[2];
    const float* scale = (const float*)d_in[3];
    float* out = (float*)d_out;

    const int B = in_sizes[0] / (ICN * IH * IW);   // 32

    dim3 block(128);
    dim3 grid(PW / 128, PH, B);
    conv_pool_clamp_kernel<<<grid, block>>>(x, w, bias, scale, out);
}

// round 4
// speedup vs baseline: 1.0091x; 1.0091x over previous
#include <cuda_runtime.h>
#include <cstdint>

// Fused: conv3x3 (zero-pad bottom/right) -> +bias -> *scale -> maxpool2x2 -> clamp[0,1]
// x: [B,3,512,512] f32, w: [16,3,3,3], bias: [16], scale: [16,1,1]
// out: [B,16,256,256] f32
//
// One thread = one pooled pixel for 8 of the 16 OC (grid.x carries the OC group).
// Packed f32x2 FMA: two horizontal conv columns per register pair.
// Halved per-thread accumulator state vs R1 -> higher occupancy.

#define OCN 16
#define OCG 8
#define ICN 3
#define IH 512
#define IW 512
#define PH 256
#define PW 256

__device__ __forceinline__ unsigned long long pack2(float a, float b) {
    unsigned long long r;
    asm("mov.b64 %0, {%1, %2};" : "=l"(r) : "f"(a), "f"(b));
    return r;
}
__device__ __forceinline__ void unpack2(unsigned long long p, float& a, float& b) {
    asm("mov.b64 {%0, %1}, %2;" : "=f"(a), "=f"(b) : "l"(p));
}
__device__ __forceinline__ void fma2(unsigned long long& acc, unsigned long long a,
                                     unsigned long long b) {
    asm("fma.rn.f32x2 %0, %1, %2, %0;" : "+l"(acc) : "l"(a), "l"(b));
}
__device__ __forceinline__ unsigned long long fma2n(unsigned long long a, unsigned long long b,
                                                    unsigned long long c) {
    unsigned long long d;
    asm("fma.rn.f32x2 %0, %1, %2, %3;" : "=l"(d) : "l"(a), "l"(b), "l"(c));
    return d;
}

__global__ __launch_bounds__(128, 5)
void conv_pool_clamp_kernel(const float* __restrict__ x,
                            const float* __restrict__ w,
                            const float* __restrict__ bias,
                            const float* __restrict__ scale,
                            float* __restrict__ out) {
    // Weights for THIS 8-OC group, pre-duplicated {w,w} for LDS.64 broadcast.
    __shared__ unsigned long long sw[OCG * ICN * 9];
    __shared__ unsigned long long ssc[OCG];   // {s, s}
    __shared__ unsigned long long sbs[OCG];   // {b*s, b*s}

    const int tid = threadIdx.x;
    const int bx  = blockIdx.x;               // 0..3: bit0 = pw half, bit1 = oc group
    const int ocbase = (bx >> 1) * OCG;

    for (int i = tid; i < OCG * ICN * 9; i += 128) {
        const int o = i / (ICN * 9);
        const int r = i % (ICN * 9);
        float v = w[(ocbase + o) * (ICN * 9) + r];
        sw[i] = pack2(v, v);
    }
    if (tid < OCG) {
        float s  = scale[ocbase + tid];
        float bs = bias[ocbase + tid] * s;
        ssc[tid] = pack2(s, s);
        sbs[tid] = pack2(bs, bs);
    }
    __syncthreads();

    const int pw = (bx & 1) * 128 + tid;      // 0..255
    const int ph = blockIdx.y;                // 0..255
    const int bi = blockIdx.z;                // 0..B-1

    const int ih0 = ph * 2;
    const int iw0 = pw * 2;

    // Per OC: top conv row (oh=2ph) and bottom conv row (oh=2ph+1),
    // each holding conv columns {2pw, 2pw+1} packed in f32x2.
    unsigned long long acc_t[OCG], acc_b[OCG];
#pragma unroll
    for (int o = 0; o < OCG; o++) { acc_t[o] = 0ull; acc_b[o] = 0ull; }

#pragma unroll
    for (int ic = 0; ic < ICN; ic++) {
        const float* xc = x + ((size_t)bi * ICN + ic) * (IH * IW);

        // 4x4 input patch (zero-padded bottom/right) -> overlapping column
        // pairs p[rr][t] = {col t, col t+1}.
        unsigned long long p[4][3];
#pragma unroll
        for (int rr = 0; rr < 4; rr++) {
            const int ih = ih0 + rr;
            float c0 = 0.f, c1 = 0.f, c2 = 0.f, c3 = 0.f;
            if (ih < IH) {
                const float* row = xc + (size_t)ih * IW;
                float2 lo = *(const float2*)(row + iw0);      // always in-bounds
                c0 = lo.x; c1 = lo.y;
                if (iw0 + 2 < IW) {                           // hi pair all-in or all-out
                    float2 hi = *(const float2*)(row + iw0 + 2);
                    c2 = hi.x; c3 = hi.y;
                }
            }
            p[rr][0] = pack2(c0, c1);
            p[rr][1] = pack2(c1, c2);
            p[rr][2] = pack2(c2, c3);
        }

#pragma unroll
        for (int oc = 0; oc < OCG; oc++) {
            const unsigned long long* wp = &sw[(oc * ICN + ic) * 9];
#pragma unroll
            for (int kh = 0; kh < 3; kh++) {
#pragma unroll
                for (int kw = 0; kw < 3; kw++) {
                    const unsigned long long w2 = wp[kh * 3 + kw];  // LDS.64 broadcast
                    fma2(acc_t[oc], p[kh][kw], w2);
                    fma2(acc_b[oc], p[kh + 1][kw], w2);
                }
            }
        }
    }

    // Epilogue: (y + bias) * scale -> max over 2x2 -> clamp [0,1]
    float* ob = out + (((size_t)(bi * OCN + ocbase)) * PH + ph) * PW + pw;
#pragma unroll
    for (int oc = 0; oc < OCG; oc++) {
        unsigned long long t = fma2n(acc_t[oc], ssc[oc], sbs[oc]);
        unsigned long long b = fma2n(acc_b[oc], ssc[oc], sbs[oc]);
        float t0, t1, b0, b1;
        unpack2(t, t0, t1);
        unpack2(b, b0, b1);
        float m = fmaxf(fmaxf(t0, t1), fmaxf(b0, b1));
        m = fminf(fmaxf(m, 0.0f), 1.0f);
        ob[(size_t)oc * (PH * PW)] = m;
    }
}

extern "C" void kernel_launch(void* const* d_in, const int* in_sizes, int n_in,
                              void* d_out, int out_size) {
    const float* x     = (const float*)d_in[0];
    const float* w     = (const float*)d_in[1];
    const float* bias  = (const float*)d_in[2];
    const float* scale = (const float*)d_in[3];
    float* out = (float*)d_out;

    const int B = in_sizes[0] / (ICN * IH * IW);   // 32

    dim3 block(128);
    dim3 grid(4, PH, B);   // x: {pw half} x {oc group}, y: pooled row, z: batch
    conv_pool_clamp_kernel<<<grid, block>>>(x, w, bias, scale, out);
}

// round 5
// speedup vs baseline: 1.0968x; 1.0869x over previous
#include <cuda_runtime.h>
#include <cstdint>

// Fused: conv3x3 (zero-pad bottom/right) -> +bias -> *scale -> maxpool2x2 -> clamp[0,1]
// x: [B,3,512,512] f32, w: [16,3,3,3], bias: [16], scale: [16,1,1]
// out: [B,16,256,256] f32
//
// One thread = a 1x2 VERTICAL pair of pooled pixels for 4 of the 16 OC.
// Packed f32x2 FMA covers the two horizontal conv columns of each pooled pixel.
// Each weight LDS.64 now feeds 4 FFMA2 (4 conv rows) -> smem crossbar no longer
// co-binds with the fma pipe (R4 finding: L1=61.5% was the limiter).

#define OCN 16
#define OCG 4
#define ICN 3
#define IH 512
#define IW 512
#define PH 256
#define PW 256

__device__ __forceinline__ unsigned long long pack2(float a, float b) {
    unsigned long long r;
    asm("mov.b64 %0, {%1, %2};" : "=l"(r) : "f"(a), "f"(b));
    return r;
}
__device__ __forceinline__ void unpack2(unsigned long long p, float& a, float& b) {
    asm("mov.b64 {%0, %1}, %2;" : "=f"(a), "=f"(b) : "l"(p));
}
__device__ __forceinline__ void fma2(unsigned long long& acc, unsigned long long a,
                                     unsigned long long b) {
    asm("fma.rn.f32x2 %0, %1, %2, %0;" : "+l"(acc) : "l"(a), "l"(b));
}
__device__ __forceinline__ unsigned long long fma2n(unsigned long long a, unsigned long long b,
                                                    unsigned long long c) {
    unsigned long long d;
    asm("fma.rn.f32x2 %0, %1, %2, %3;" : "=l"(d) : "l"(a), "l"(b), "l"(c));
    return d;
}

__global__ __launch_bounds__(128, 5)
void conv_pool_clamp_kernel(const float* __restrict__ x,
                            const float* __restrict__ w,
                            const float* __restrict__ bias,
                            const float* __restrict__ scale,
                            float* __restrict__ out) {
    // Weights for THIS 4-OC group, pre-duplicated {w,w} for LDS.64 broadcast.
    __shared__ unsigned long long sw[OCG * ICN * 9];
    __shared__ unsigned long long ssc[OCG];   // {s, s}
    __shared__ unsigned long long sbs[OCG];   // {b*s, b*s}

    const int tid = threadIdx.x;
    const int bx  = blockIdx.x;               // 0..7: bit0 = pw half, bits[1:2] = oc group
    const int ocbase = (bx >> 1) * OCG;

    for (int i = tid; i < OCG * ICN * 9; i += 128) {
        float v = w[ocbase * (ICN * 9) + i];
        sw[i] = pack2(v, v);
    }
    if (tid < OCG) {
        float s  = scale[ocbase + tid];
        float bs = bias[ocbase + tid] * s;
        ssc[tid] = pack2(s, s);
        sbs[tid] = pack2(bs, bs);
    }
    __syncthreads();

    const int pw  = (bx & 1) * 128 + tid;     // 0..255
    const int phb = blockIdx.y;               // 0..127 : pooled-row PAIR index
    const int bi  = blockIdx.z;               // 0..B-1

    const int ih0 = phb * 4;                  // first input row of the 6-row patch
    const int iw0 = pw * 2;

    // acc[oc][cr]: conv output row (4*phb + cr), cr=0..3, columns {2pw,2pw+1} packed.
    unsigned long long acc[OCG][4];
#pragma unroll
    for (int o = 0; o < OCG; o++)
#pragma unroll
        for (int c = 0; c < 4; c++) acc[o][c] = 0ull;

#pragma unroll
    for (int ic = 0; ic < ICN; ic++) {
        const float* xc = x + ((size_t)bi * ICN + ic) * (IH * IW);

        // 6x4 input patch (zero-padded bottom/right) -> overlapping column pairs.
        unsigned long long p[6][3];
#pragma unroll
        for (int rr = 0; rr < 6; rr++) {
            const int ih = ih0 + rr;
            float c0 = 0.f, c1 = 0.f, c2 = 0.f, c3 = 0.f;
            if (ih < IH) {
                const float* row = xc + (size_t)ih * IW;
                float2 lo = *(const float2*)(row + iw0);      // always in-bounds
                c0 = lo.x; c1 = lo.y;
                if (iw0 + 2 < IW) {                           // hi pair all-in or all-out
                    float2 hi = *(const float2*)(row + iw0 + 2);
                    c2 = hi.x; c3 = hi.y;
                }
            }
            p[rr][0] = pack2(c0, c1);
            p[rr][1] = pack2(c1, c2);
            p[rr][2] = pack2(c2, c3);
        }

#pragma unroll
        for (int oc = 0; oc < OCG; oc++) {
            const unsigned long long* wp = &sw[(oc * ICN + ic) * 9];
#pragma unroll
            for (int kh = 0; kh < 3; kh++) {
#pragma unroll
                for (int kw = 0; kw < 3; kw++) {
                    const unsigned long long w2 = wp[kh * 3 + kw];  // 1 LDS.64 -> 4 FFMA2
                    fma2(acc[oc][0], p[kh + 0][kw], w2);
                    fma2(acc[oc][1], p[kh + 1][kw], w2);
                    fma2(acc[oc][2], p[kh + 2][kw], w2);
                    fma2(acc[oc][3], p[kh + 3][kw], w2);
                }
            }
        }
    }

    // Epilogue: (y + bias) * scale -> max over 2x2 -> clamp [0,1]; two pooled rows.
    const int ph0 = phb * 2;
    float* ob = out + (((size_t)(bi * OCN + ocbase)) * PH + ph0) * PW + pw;
#pragma unroll
    for (int oc = 0; oc < OCG; oc++) {
        float v0, v1, v2, v3;
        // pooled pixel 0: conv rows 0,1
        unsigned long long t = fma2n(acc[oc][0], ssc[oc], sbs[oc]);
        unsigned long long b = fma2n(acc[oc][1], ssc[oc], sbs[oc]);
        unpack2(t, v0, v1); unpack2(b, v2, v3);
        float m0 = fmaxf(fmaxf(v0, v1), fmaxf(v2, v3));
        m0 = fminf(fmaxf(m0, 0.0f), 1.0f);
        // pooled pixel 1: conv rows 2,3
        t = fma2n(acc[oc][2], ssc[oc], sbs[oc]);
        b = fma2n(acc[oc][3], ssc[oc], sbs[oc]);
        unpack2(t, v0, v1); unpack2(b, v2, v3);
        float m1 = fmaxf(fmaxf(v0, v1), fmaxf(v2, v3));
        m1 = fminf(fmaxf(m1, 0.0f), 1.0f);

        float* oc_ptr = ob + (size_t)oc * (PH * PW);
        oc_ptr[0]  = m0;
        oc_ptr[PW] = m1;
    }
}

extern "C" void kernel_launch(void* const* d_in, const int* in_sizes, int n_in,
                              void* d_out, int out_size) {
    const float* x     = (const float*)d_in[0];
    const float* w     = (const float*)d_in[1];
    const float* bias  = (const float*)d_in[2];
    const float* scale = (const float*)d_in[3];
    float* out = (float*)d_out;

    const int B = in_sizes[0] / (ICN * IH * IW);   // 32

    dim3 block(128);
    dim3 grid(8, PH / 2, B);   // x: {pw half} x {4 oc groups}, y: pooled-row pair, z: batch
    conv_pool_clamp_kernel<<<grid, block>>>(x, w, bias, scale, out);
}

// round 6
// speedup vs baseline: 1.1177x; 1.0190x over previous
#include <cuda_runtime.h>
#include <cstdint>

// Fused: conv3x3 (zero-pad bottom/right) -> +bias -> *scale -> maxpool2x2 -> clamp[0,1]
// x: [B,3,512,512] f32, w: [16,3,3,3], bias: [16], scale: [16,1,1]
// out: [B,16,256,256] f32
//
// One thread = a 1x2 VERTICAL pair of pooled pixels for 4 of the 16 OC.
// Packed f32x2 FMA; each weight LDS.64 feeds 4 FFMA2.
// R5 changes: direct 64-bit loads of the aligned column pairs (kills pack MOVs),
// __launch_bounds__(128,6) to break the 5-block register wall (occ 29%->37.5%).

typedef unsigned long long ull;

#define OCN 16
#define OCG 4
#define ICN 3
#define IH 512
#define IW 512
#define PH 256
#define PW 256

__device__ __forceinline__ ull pack2(float a, float b) {
    ull r;
    asm("mov.b64 %0, {%1, %2};" : "=l"(r) : "f"(a), "f"(b));
    return r;
}
__device__ __forceinline__ void unpack2(ull p, float& a, float& b) {
    asm("mov.b64 {%0, %1}, %2;" : "=f"(a), "=f"(b) : "l"(p));
}
// {hi(lo-pair), lo(hi-pair)} — the straddling middle column pair.
__device__ __forceinline__ ull midpair(ull lo, ull hi) {
    ull r;
    asm("{\n\t"
        ".reg .b32 a, b, c, d;\n\t"
        "mov.b64 {a, b}, %1;\n\t"
        "mov.b64 {c, d}, %2;\n\t"
        "mov.b64 %0, {b, c};\n\t"
        "}" : "=l"(r) : "l"(lo), "l"(hi));
    return r;
}
__device__ __forceinline__ void fma2(ull& acc, ull a, ull b) {
    asm("fma.rn.f32x2 %0, %1, %2, %0;" : "+l"(acc) : "l"(a), "l"(b));
}
__device__ __forceinline__ ull fma2n(ull a, ull b, ull c) {
    ull d;
    asm("fma.rn.f32x2 %0, %1, %2, %3;" : "=l"(d) : "l"(a), "l"(b), "l"(c));
    return d;
}

__global__ __launch_bounds__(128, 6)
void conv_pool_clamp_kernel(const float* __restrict__ x,
                            const float* __restrict__ w,
                            const float* __restrict__ bias,
                            const float* __restrict__ scale,
                            float* __restrict__ out) {
    // Weights for THIS 4-OC group, pre-duplicated {w,w} for LDS.64 broadcast.
    __shared__ ull sw[OCG * ICN * 9];
    __shared__ ull ssc[OCG];   // {s, s}
    __shared__ ull sbs[OCG];   // {b*s, b*s}

    const int tid = threadIdx.x;
    const int bx  = blockIdx.x;               // bit0 = pw half, bits[2:1] = oc group
    const int ocbase = (bx >> 1) * OCG;

    for (int i = tid; i < OCG * ICN * 9; i += 128) {
        float v = w[ocbase * (ICN * 9) + i];
        sw[i] = pack2(v, v);
    }
    if (tid < OCG) {
        float s  = scale[ocbase + tid];
        float bs = bias[ocbase + tid] * s;
        ssc[tid] = pack2(s, s);
        sbs[tid] = pack2(bs, bs);
    }
    __syncthreads();

    const int pw  = (bx & 1) * 128 + tid;     // 0..255
    const int phb = blockIdx.y;               // 0..127 : pooled-row PAIR index
    const int bi  = blockIdx.z;               // 0..B-1

    const int ih0 = phb * 4;                  // first input row of the 6-row patch
    const int iw0 = pw * 2;

    // acc[oc][cr]: conv output row (4*phb + cr), columns {2pw,2pw+1} packed.
    ull acc[OCG][4];
#pragma unroll
    for (int o = 0; o < OCG; o++)
#pragma unroll
        for (int c = 0; c < 4; c++) acc[o][c] = 0ull;

#pragma unroll
    for (int ic = 0; ic < ICN; ic++) {
        const float* xc = x + ((size_t)bi * ICN + ic) * (IH * IW);

        // 6x4 patch as overlapping column pairs. Aligned pairs load directly
        // as 64-bit words (iw0 even -> 8B aligned); only the middle pair is built.
        ull p[6][3];
#pragma unroll
        for (int rr = 0; rr < 6; rr++) {
            ull lo = 0ull, hi = 0ull;
            const int ih = ih0 + rr;
            if (ih < IH) {
                const float* row = xc + (size_t)ih * IW + iw0;
                lo = *(const ull*)row;                    // {c0, c1}
                if (iw0 + 2 < IW) hi = *(const ull*)(row + 2);  // {c2, c3}
            }
            p[rr][0] = lo;
            p[rr][1] = midpair(lo, hi);                   // {c1, c2}
            p[rr][2] = hi;
        }

#pragma unroll
        for (int oc = 0; oc < OCG; oc++) {
            const ull* wp = &sw[(oc * ICN + ic) * 9];
#pragma unroll
            for (int kh = 0; kh < 3; kh++) {
#pragma unroll
                for (int kw = 0; kw < 3; kw++) {
                    const ull w2 = wp[kh * 3 + kw];       // 1 LDS.64 -> 4 FFMA2
                    fma2(acc[oc][0], p[kh + 0][kw], w2);
                    fma2(acc[oc][1], p[kh + 1][kw], w2);
                    fma2(acc[oc][2], p[kh + 2][kw], w2);
                    fma2(acc[oc][3], p[kh + 3][kw], w2);
                }
            }
        }
    }

    // Epilogue: (y + bias) * scale -> max over 2x2 -> clamp [0,1]; two pooled rows.
    const int ph0 = phb * 2;
    float* ob = out + (((size_t)(bi * OCN + ocbase)) * PH + ph0) * PW + pw;
#pragma unroll
    for (int oc = 0; oc < OCG; oc++) {
        float v0, v1, v2, v3;
        ull t = fma2n(acc[oc][0], ssc[oc], sbs[oc]);
        ull b = fma2n(acc[oc][1], ssc[oc], sbs[oc]);
        unpack2(t, v0, v1); unpack2(b, v2, v3);
        float m0 = fminf(fmaxf(fmaxf(fmaxf(v0, v1), fmaxf(v2, v3)), 0.0f), 1.0f);

        t = fma2n(acc[oc][2], ssc[oc], sbs[oc]);
        b = fma2n(acc[oc][3], ssc[oc], sbs[oc]);
        unpack2(t, v0, v1); unpack2(b, v2, v3);
        float m1 = fminf(fmaxf(fmaxf(fmaxf(v0, v1), fmaxf(v2, v3)), 0.0f), 1.0f);

        float* oc_ptr = ob + (size_t)oc * (PH * PW);
        oc_ptr[0]  = m0;
        oc_ptr[PW] = m1;
    }
}

extern "C" void kernel_launch(void* const* d_in, const int* in_sizes, int n_in,
                              void* d_out, int out_size) {
    const float* x     = (const float*)d_in[0];
    const float* w     = (const float*)d_in[1];
    const float* bias  = (const float*)d_in[2];
    const float* scale = (const float*)d_in[3];
    float* out = (float*)d_out;

    const int B = in_sizes[0] / (ICN * IH * IW);   // 32

    dim3 block(128);
    dim3 grid(8, PH / 2, B);   // x: {pw half} x {4 oc groups}, y: pooled-row pair, z: batch
    conv_pool_clamp_kernel<<<grid, block>>>(x, w, bias, scale, out);
}